// round 1
// baseline (speedup 1.0000x reference)
#include <cuda_runtime.h>
#include <math_constants.h>

#define NTOK 8192
#define HEADS 12
#define DQ 64
#define ROWSTRIDE 768   // HEADS*DQ floats between consecutive tokens

// denominator buffer: per (b, head, d) sums  (2*12*64)
__device__ float g_denom[2 * HEADS * DQ];

__device__ __forceinline__ float fast_exp2(float x) {
    float y;
    asm("ex2.approx.ftz.f32 %0, %1;" : "=f"(y) : "f"(x));
    return y;
}

// ---------------------------------------------------------------------------
// Kernel 1: flash attention per (group, b, seg, head) x q-tile(64 rows).
// All three groups have dilated seq length 2048. Writes RAW attention output
// (softmax-normalized, before the cross-position sum normalization) to the
// scattered covered positions of out.
// ---------------------------------------------------------------------------
__global__ void __launch_bounds__(64) attn_kernel(
    const float* __restrict__ Q,
    const float* __restrict__ K,
    const float* __restrict__ V,
    float* __restrict__ out)
{
    __shared__ float KV[64 * 64];     // K tile, then reused for V tile
    __shared__ float Ss[64 * 65];     // score tile, row stride 65 (conflict-free)

    const int job = blockIdx.y;       // 0..55
    int g, b, seg, hl;
    if (job < 32)      { g = 0; hl = job & 3;  seg = (job >> 2) & 3; b = job >> 4; }
    else if (job < 48) { int l = job - 32; g = 1; hl = l & 3; seg = (l >> 2) & 1; b = l >> 3; }
    else               { int l = job - 48; g = 2; hl = l & 3; seg = 0;            b = l >> 2; }

    const int r      = 1 << g;            // dilation 1,2,4
    const int s      = 2048 << g;         // segment 2048,4096,8192
    const int off    = (g == 2) ? 2 : g;  // offset 0,1,2
    const int h      = g * 4 + hl;
    const int tid    = threadIdx.x;
    const int rstride = r * ROWSTRIDE;    // float stride between dilated tokens

    const long segbase = ((long)b * NTOK + (long)seg * s + off) * ROWSTRIDE + h * DQ;

    // ---- load my Q row into registers, pre-scaled by (1/8)*log2(e) ----
    float q[64];
    {
        const float4* qp = (const float4*)(Q + segbase + (long)(blockIdx.x * 64 + tid) * rstride);
        const float qs = 0.125f * 1.4426950408889634f;
        #pragma unroll
        for (int c = 0; c < 16; c++) {
            float4 t = qp[c];
            q[4*c+0] = t.x * qs; q[4*c+1] = t.y * qs;
            q[4*c+2] = t.z * qs; q[4*c+3] = t.w * qs;
        }
    }

    float o[64];
    #pragma unroll
    for (int d = 0; d < 64; d++) o[d] = 0.f;
    float m = -CUDART_INF_F;
    float l = 0.f;

    for (int kt = 0; kt < 32; kt++) {
        __syncthreads();  // previous pass-B done reading KV
        // ---- stage K tile (64 rows x 64 d), coalesced 256B per row-chunk ----
        {
            const float* kbase = K + segbase + (long)(kt * 64) * rstride;
            #pragma unroll
            for (int it = 0; it < 16; it++) {
                int idx = tid + it * 64;
                int row = idx >> 4, c = idx & 15;
                ((float4*)KV)[row * 16 + c] =
                    ((const float4*)(kbase + (long)row * rstride))[c];
            }
        }
        __syncthreads();

        // ---- pass A: scores for my row ----
        float tmax = -CUDART_INF_F;
        #pragma unroll 2
        for (int j = 0; j < 64; j++) {
            float a0 = 0.f, a1 = 0.f, a2 = 0.f, a3 = 0.f;
            #pragma unroll
            for (int c = 0; c < 16; c++) {
                float4 k4 = ((const float4*)KV)[j * 16 + c];   // broadcast
                a0 += q[4*c+0] * k4.x; a1 += q[4*c+1] * k4.y;
                a2 += q[4*c+2] * k4.z; a3 += q[4*c+3] * k4.w;
            }
            float sc = (a0 + a1) + (a2 + a3);
            tmax = fmaxf(tmax, sc);
            Ss[tid * 65 + j] = sc;
        }

        // ---- online softmax rescale ----
        float mnew  = fmaxf(m, tmax);
        float scale = fast_exp2(m - mnew);   // exp2(-inf)=0 handles first tile
        m = mnew;
        l *= scale;
        #pragma unroll
        for (int d = 0; d < 64; d++) o[d] *= scale;

        __syncthreads();  // pass-A done reading K from KV
        // ---- stage V tile ----
        {
            const float* vbase = V + segbase + (long)(kt * 64) * rstride;
            #pragma unroll
            for (int it = 0; it < 16; it++) {
                int idx = tid + it * 64;
                int row = idx >> 4, c = idx & 15;
                ((float4*)KV)[row * 16 + c] =
                    ((const float4*)(vbase + (long)row * rstride))[c];
            }
        }
        __syncthreads();

        // ---- pass B: P*V accumulate ----
        #pragma unroll 2
        for (int j = 0; j < 64; j++) {
            float p = fast_exp2(Ss[tid * 65 + j] - m);
            l += p;
            #pragma unroll
            for (int c = 0; c < 16; c++) {
                float4 v4 = ((const float4*)KV)[j * 16 + c];   // broadcast
                o[4*c+0] += p * v4.x; o[4*c+1] += p * v4.y;
                o[4*c+2] += p * v4.z; o[4*c+3] += p * v4.w;
            }
        }
    }

    // ---- epilogue: normalize by l, write raw attention output ----
    float invl = 1.f / l;
    float4* op = (float4*)(out + segbase + (long)(blockIdx.x * 64 + tid) * rstride);
    #pragma unroll
    for (int c = 0; c < 16; c++) {
        float4 w;
        w.x = o[4*c+0] * invl; w.y = o[4*c+1] * invl;
        w.z = o[4*c+2] * invl; w.w = o[4*c+3] * invl;
        op[c] = w;
    }
}

// ---------------------------------------------------------------------------
// Kernel 2: deterministic per-(b,h,d) sum over all covered positions.
// Covered n for head-group g are exactly { n : n mod r == off }.
// One block per (b,h); 512 threads = 64 d-channels x 8 slices.
// ---------------------------------------------------------------------------
__global__ void __launch_bounds__(512) denom_kernel(const float* __restrict__ out)
{
    __shared__ float red[512];
    const int bh = blockIdx.x;           // 0..23
    const int b  = bh / HEADS;
    const int h  = bh % HEADS;
    const int g  = h >> 2;
    const int r  = 1 << g;
    const int off = (g == 2) ? 2 : g;

    const int tid   = threadIdx.x;
    const int d     = tid & 63;
    const int slice = tid >> 6;          // 0..7
    const int count = NTOK >> g;         // covered positions

    const float* p = out + ((long)b * NTOK + off) * ROWSTRIDE + h * DQ + d;
    float acc = 0.f;
    for (int t = slice; t < count; t += 8)
        acc += p[(long)t * r * ROWSTRIDE];

    red[tid] = acc;
    __syncthreads();
    if (slice == 0) {
        float sum = red[d];
        #pragma unroll
        for (int k = 1; k < 8; k++) sum += red[k * 64 + d];
        g_denom[bh * DQ + d] = sum;
    }
}

// ---------------------------------------------------------------------------
// Kernel 3: final elementwise pass over the whole output tensor.
// Covered: out = raw / (denom * 3). Uncovered: 0 (also clears the 0xAA poison).
// ---------------------------------------------------------------------------
__global__ void __launch_bounds__(256) norm_kernel(float* __restrict__ out)
{
    const long total = (long)2 * NTOK * HEADS * DQ;
    long idx = (long)blockIdx.x * 256 + threadIdx.x;
    if (idx >= total) return;

    int  d = (int)(idx & 63);
    long t = idx >> 6;
    int  h = (int)(t % HEADS); t /= HEADS;
    int  n = (int)(t % NTOK);
    int  b = (int)(t / NTOK);

    int g   = h >> 2;
    int r   = 1 << g;
    int off = (g == 2) ? 2 : g;

    float v = 0.f;
    if ((n & (r - 1)) == off) {
        v = out[idx] / (g_denom[(b * HEADS + h) * DQ + d] * 3.0f);
    }
    out[idx] = v;
}

// ---------------------------------------------------------------------------
extern "C" void kernel_launch(void* const* d_in, const int* in_sizes, int n_in,
                              void* d_out, int out_size)
{
    const float* Q = (const float*)d_in[0];
    const float* K = (const float*)d_in[1];
    const float* V = (const float*)d_in[2];
    float* out = (float*)d_out;

    attn_kernel<<<dim3(32, 56), 64>>>(Q, K, V, out);
    denom_kernel<<<2 * HEADS, 512>>>(out);

    const long total = (long)2 * NTOK * HEADS * DQ;
    int blocks = (int)((total + 255) / 256);
    norm_kernel<<<blocks, 256>>>(out);
}

// round 12
// speedup vs baseline: 2.1794x; 2.1794x over previous
#include <cuda_runtime.h>
#include <cuda_fp16.h>
#include <cstdint>

#define NTOK 8192
#define HEADS 12
#define ROWSTRIDE 768   // HEADS*64 floats between consecutive tokens

__device__ float g_denom[2 * HEADS * 64];

// ---------------------------------------------------------------------------
// helpers
// ---------------------------------------------------------------------------
__device__ __forceinline__ float fast_exp2(float x) {
    float y; asm("ex2.approx.ftz.f32 %0, %1;" : "=f"(y) : "f"(x)); return y;
}
// pack two f32 -> f16x2 (lo = low 16 bits)
__device__ __forceinline__ uint32_t packh2(float lo, float hi) {
    uint32_t r;
    asm("cvt.rn.f16x2.f32 %0, %1, %2;" : "=r"(r) : "f"(hi), "f"(lo));
    return r;
}
// unpack f16x2 -> two f32
__device__ __forceinline__ float2 unpackh2(uint32_t p) {
    __half2 h = *reinterpret_cast<__half2*>(&p);
    return __half22float2(h);
}
__device__ __forceinline__ uint32_t smem_u32(const void* p) {
    uint32_t a;
    asm("{ .reg .u64 t; cvta.to.shared.u64 t, %1; cvt.u32.u64 %0, t; }" : "=r"(a) : "l"(p));
    return a;
}
__device__ __forceinline__ void ldsm4(uint32_t r[4], uint32_t addr) {
    asm volatile("ldmatrix.sync.aligned.m8n8.x4.shared.b16 {%0,%1,%2,%3}, [%4];"
                 : "=r"(r[0]), "=r"(r[1]), "=r"(r[2]), "=r"(r[3]) : "r"(addr));
}
__device__ __forceinline__ void mma16816(float d[4], const uint32_t a[4],
                                         uint32_t b0, uint32_t b1, const float c[4]) {
    asm volatile(
        "mma.sync.aligned.m16n8k16.row.col.f32.f16.f16.f32 "
        "{%0,%1,%2,%3},{%4,%5,%6,%7},{%8,%9},{%10,%11,%12,%13};"
        : "=f"(d[0]), "=f"(d[1]), "=f"(d[2]), "=f"(d[3])
        : "r"(a[0]), "r"(a[1]), "r"(a[2]), "r"(a[3]), "r"(b0), "r"(b1),
          "f"(c[0]), "f"(c[1]), "f"(c[2]), "f"(c[3]));
}

// swizzled byte offset of (row, 16B-chunk) in a [rows][64 half] tile (128B/row)
#define SWB(row, c8) (((uint32_t)(row) << 7) + ((((uint32_t)(c8)) ^ ((uint32_t)(row) & 7u)) << 4))
// swizzled byte offset of (d-row, 16B-chunk) in Vt [64 d][128 half] tile (256B/row)
#define VTB(d, c16) (((uint32_t)(d) << 8) + ((((uint32_t)(c16)) ^ (((uint32_t)(d) & 7u) << 1)) << 4))

#define SMEM_BYTES (5 * 16384)

#define C11 (1.0f / 2048.0f)
#define C22 (C11 * C11)

// ---------------------------------------------------------------------------
// Kernel 1: mma.sync scaled-split-fp16 flash attention (~fp32 accuracy).
// CTA = (q-tile of 128 rows, job). 8 warps x 16 rows. BLOCK_N = 128.
// x = hi + lo2/2048 with lo2 = (x-hi)*2048 (exact scale, full residual bits).
// GEMM1: hh + (h*lo2 + lo2*h)*2^-11 + lo2*lo2*2^-22   (fp32-grade products)
// GEMM2: hh + (ph*vlo2 + plo2*vh + plo2*vlo_unscaled)*2^-11
// ---------------------------------------------------------------------------
__global__ void __launch_bounds__(256) attn_kernel(
    const float* __restrict__ Q,
    const float* __restrict__ K,
    const float* __restrict__ V,
    float* __restrict__ out)
{
    extern __shared__ __align__(16) char smem_raw[];
    const uint32_t aKh = smem_u32(smem_raw);
    const uint32_t aKl = aKh + 16384;   // K residual *2048
    const uint32_t aVh = aKh + 32768;
    const uint32_t aVl = aKh + 49152;   // V residual *2048
    const uint32_t aVu = aKh + 65536;   // V residual unscaled

    const int tid  = threadIdx.x;
    const int wid  = tid >> 5;
    const int lane = tid & 31;

    // ---- decode job ----
    const int job = blockIdx.y;
    int g, b, seg, hl;
    if (job < 32)      { g = 0; hl = job & 3;  seg = (job >> 2) & 3; b = job >> 4; }
    else if (job < 48) { int l = job - 32; g = 1; hl = l & 3; seg = (l >> 2) & 1; b = l >> 3; }
    else               { int l = job - 48; g = 2; hl = l & 3; seg = 0;            b = l >> 2; }
    const int r   = 1 << g;
    const int s   = 2048 << g;
    const int off = (g == 2) ? 2 : g;
    const int h   = g * 4 + hl;
    const long rstride = (long)r * ROWSTRIDE;
    const long segbase = ((long)b * NTOK + (long)seg * s + off) * ROWSTRIDE + h * 64;
    const long qbase   = segbase + (long)blockIdx.x * 128 * rstride;

    // ---- stage Q (pre-scaled): hi into aKh, residual*2048 into aKl ----
    const float qs = 0.125f * 1.4426950408889634f;
    #pragma unroll
    for (int i = 0; i < 8; i++) {
        int linear = tid + (i << 8);
        int row = linear >> 4, f4 = linear & 15;
        float4 v = *(const float4*)(Q + qbase + (long)row * rstride + (f4 << 2));
        v.x *= qs; v.y *= qs; v.z *= qs; v.w *= qs;
        uint32_t h0 = packh2(v.x, v.y), h1 = packh2(v.z, v.w);
        float2 f0 = unpackh2(h0), f1 = unpackh2(h1);
        uint32_t l0_ = packh2((v.x - f0.x) * 2048.f, (v.y - f0.y) * 2048.f);
        uint32_t l1_ = packh2((v.z - f1.x) * 2048.f, (v.w - f1.y) * 2048.f);
        uint32_t o8 = SWB(row, f4 >> 1) + ((uint32_t)(f4 & 1) << 3);
        asm volatile("st.shared.v2.b32 [%0], {%1,%2};" :: "r"(aKh + o8), "r"(h0), "r"(h1));
        asm volatile("st.shared.v2.b32 [%0], {%1,%2};" :: "r"(aKl + o8), "r"(l0_), "r"(l1_));
    }
    __syncthreads();

    uint32_t qfh[4][4], qfl[4][4];   // qfl holds scaled residual fragments
    {
        uint32_t row = (uint32_t)(wid * 16 + (lane & 15));
        #pragma unroll
        for (int ks = 0; ks < 4; ks++) {
            uint32_t chunk = (uint32_t)(lane >> 4) + ((uint32_t)ks << 1);
            ldsm4(qfh[ks], aKh + SWB(row, chunk));
            ldsm4(qfl[ks], aKl + SWB(row, chunk));
        }
    }
    __syncthreads();   // fragments in registers before K overwrites the buffers

    float oacc[8][4];
    #pragma unroll
    for (int i = 0; i < 8; i++)
        #pragma unroll
        for (int e = 0; e < 4; e++) oacc[i][e] = 0.f;
    float lr0 = 0.f, lr1 = 0.f;

    for (int kt = 0; kt < 16; kt++) {
        __syncthreads();
        // ---- stage K tile: hi + residual*2048 ----
        {
            const float* kb = K + segbase + (long)(kt * 128) * rstride;
            #pragma unroll
            for (int i = 0; i < 8; i++) {
                int linear = tid + (i << 8);
                int row = linear >> 4, f4 = linear & 15;
                float4 v = *(const float4*)(kb + (long)row * rstride + (f4 << 2));
                uint32_t h0 = packh2(v.x, v.y), h1 = packh2(v.z, v.w);
                float2 f0 = unpackh2(h0), f1 = unpackh2(h1);
                uint32_t l0_ = packh2((v.x - f0.x) * 2048.f, (v.y - f0.y) * 2048.f);
                uint32_t l1_ = packh2((v.z - f1.x) * 2048.f, (v.w - f1.y) * 2048.f);
                uint32_t o8 = SWB(row, f4 >> 1) + ((uint32_t)(f4 & 1) << 3);
                asm volatile("st.shared.v2.b32 [%0], {%1,%2};" :: "r"(aKh + o8), "r"(h0), "r"(h1));
                asm volatile("st.shared.v2.b32 [%0], {%1,%2};" :: "r"(aKl + o8), "r"(l0_), "r"(l1_));
            }
        }
        // ---- stage V TRANSPOSED: hi, residual*2048, residual unscaled ----
        {
            const float* vb = V + segbase + (long)(kt * 128) * rstride;
            #pragma unroll
            for (int i = 0; i < 16; i++) {
                int p  = tid + (i << 8);
                int d  = p & 63;
                int jp = p >> 6;
                float v0 = vb[(long)(2 * jp)     * rstride + d];
                float v1 = vb[(long)(2 * jp + 1) * rstride + d];
                uint32_t hp = packh2(v0, v1);
                float2 hf = unpackh2(hp);
                float r0 = v0 - hf.x, r1 = v1 - hf.y;
                uint32_t lp = packh2(r0 * 2048.f, r1 * 2048.f);
                uint32_t up = packh2(r0, r1);
                uint32_t ob = VTB(d, jp >> 2) + (((uint32_t)jp & 3u) << 2);
                asm volatile("st.shared.b32 [%0], %1;" :: "r"(aVh + ob), "r"(hp));
                asm volatile("st.shared.b32 [%0], %1;" :: "r"(aVl + ob), "r"(lp));
                asm volatile("st.shared.b32 [%0], %1;" :: "r"(aVu + ob), "r"(up));
            }
        }
        __syncthreads();

        // ---- S = Q @ K^T  (hh + cor*2^-11 + ll*2^-22) ----
        float sacc[16][4];
        #pragma unroll
        for (int np = 0; np < 8; np++) {
            float a0[2][4], a1[2][4], a2[2][4];
            #pragma unroll
            for (int hh = 0; hh < 2; hh++)
                #pragma unroll
                for (int e = 0; e < 4; e++) { a0[hh][e] = 0.f; a1[hh][e] = 0.f; a2[hh][e] = 0.f; }

            uint32_t row = ((uint32_t)np << 4) + (uint32_t)(lane & 15);
            #pragma unroll
            for (int ks = 0; ks < 4; ks++) {
                uint32_t chunk = (uint32_t)(lane >> 4) + ((uint32_t)ks << 1);
                uint32_t kh[4], kl[4];
                ldsm4(kh, aKh + SWB(row, chunk));
                ldsm4(kl, aKl + SWB(row, chunk));
                mma16816(a0[0], qfh[ks], kh[0], kh[2], a0[0]);
                mma16816(a0[1], qfh[ks], kh[1], kh[3], a0[1]);
                mma16816(a1[0], qfh[ks], kl[0], kl[2], a1[0]);
                mma16816(a1[1], qfh[ks], kl[1], kl[3], a1[1]);
                mma16816(a1[0], qfl[ks], kh[0], kh[2], a1[0]);
                mma16816(a1[1], qfl[ks], kh[1], kh[3], a1[1]);
                mma16816(a2[0], qfl[ks], kl[0], kl[2], a2[0]);
                mma16816(a2[1], qfl[ks], kl[1], kl[3], a2[1]);
            }
            #pragma unroll
            for (int e = 0; e < 4; e++) {
                sacc[2*np][e]   = a0[0][e] + a1[0][e] * C11 + a2[0][e] * C22;
                sacc[2*np+1][e] = a0[1][e] + a1[1][e] * C11 + a2[1][e] * C22;
            }
        }

        // ---- softmax + O += P @ V (split P and V, correction accumulator) ----
        float ocor[8][4];
        #pragma unroll
        for (int i = 0; i < 8; i++)
            #pragma unroll
            for (int e = 0; e < 4; e++) ocor[i][e] = 0.f;

        #pragma unroll
        for (int j = 0; j < 8; j++) {
            uint32_t pfh[4], pfl[4];
            {
                float p0 = fast_exp2(sacc[2*j][0]);
                float p1 = fast_exp2(sacc[2*j][1]);
                float p2 = fast_exp2(sacc[2*j][2]);
                float p3 = fast_exp2(sacc[2*j][3]);
                float p4 = fast_exp2(sacc[2*j+1][0]);
                float p5 = fast_exp2(sacc[2*j+1][1]);
                float p6 = fast_exp2(sacc[2*j+1][2]);
                float p7 = fast_exp2(sacc[2*j+1][3]);
                lr0 += (p0 + p1) + (p4 + p5);
                lr1 += (p2 + p3) + (p6 + p7);
                pfh[0] = packh2(p0, p1);
                pfh[1] = packh2(p2, p3);
                pfh[2] = packh2(p4, p5);
                pfh[3] = packh2(p6, p7);
                float2 f;
                f = unpackh2(pfh[0]); pfl[0] = packh2((p0 - f.x) * 2048.f, (p1 - f.y) * 2048.f);
                f = unpackh2(pfh[1]); pfl[1] = packh2((p2 - f.x) * 2048.f, (p3 - f.y) * 2048.f);
                f = unpackh2(pfh[2]); pfl[2] = packh2((p4 - f.x) * 2048.f, (p5 - f.y) * 2048.f);
                f = unpackh2(pfh[3]); pfl[3] = packh2((p6 - f.x) * 2048.f, (p7 - f.y) * 2048.f);
            }
            #pragma unroll
            for (int dp = 0; dp < 4; dp++) {
                uint32_t drow  = ((uint32_t)dp << 4) + (uint32_t)(lane & 15);
                uint32_t chunk = (uint32_t)(lane >> 4) + ((uint32_t)j << 1);
                uint32_t vh[4], vl[4], vu[4];
                ldsm4(vh, aVh + VTB(drow, chunk));
                ldsm4(vl, aVl + VTB(drow, chunk));
                ldsm4(vu, aVu + VTB(drow, chunk));
                mma16816(oacc[2*dp],   pfh, vh[0], vh[2], oacc[2*dp]);
                mma16816(oacc[2*dp+1], pfh, vh[1], vh[3], oacc[2*dp+1]);
                mma16816(ocor[2*dp],   pfh, vl[0], vl[2], ocor[2*dp]);
                mma16816(ocor[2*dp+1], pfh, vl[1], vl[3], ocor[2*dp+1]);
                mma16816(ocor[2*dp],   pfl, vh[0], vh[2], ocor[2*dp]);
                mma16816(ocor[2*dp+1], pfl, vh[1], vh[3], ocor[2*dp+1]);
                mma16816(ocor[2*dp],   pfl, vu[0], vu[2], ocor[2*dp]);
                mma16816(ocor[2*dp+1], pfl, vu[1], vu[3], ocor[2*dp+1]);
            }
        }
        // fold correction into main accumulator
        #pragma unroll
        for (int i = 0; i < 8; i++)
            #pragma unroll
            for (int e = 0; e < 4; e++)
                oacc[i][e] = fmaf(ocor[i][e], C11, oacc[i][e]);
    }

    // ---- epilogue: reduce l across quad, normalize, write ----
    lr0 += __shfl_xor_sync(0xffffffffu, lr0, 1);
    lr0 += __shfl_xor_sync(0xffffffffu, lr0, 2);
    lr1 += __shfl_xor_sync(0xffffffffu, lr1, 1);
    lr1 += __shfl_xor_sync(0xffffffffu, lr1, 2);
    const float inv0 = 1.f / lr0;
    const float inv1 = 1.f / lr1;

    const int gq = lane >> 2, t4 = lane & 3;
    float* r0p = out + qbase + (long)(wid * 16 + gq) * rstride;
    float* r1p = out + qbase + (long)(wid * 16 + gq + 8) * rstride;
    #pragma unroll
    for (int dt = 0; dt < 8; dt++) {
        float2 w0 = make_float2(oacc[dt][0] * inv0, oacc[dt][1] * inv0);
        float2 w1 = make_float2(oacc[dt][2] * inv1, oacc[dt][3] * inv1);
        *(float2*)(r0p + dt * 8 + 2 * t4) = w0;
        *(float2*)(r1p + dt * 8 + 2 * t4) = w1;
    }
}

// ---------------------------------------------------------------------------
// Kernel 2: deterministic per-(b,h,d) sum over covered positions.
// ---------------------------------------------------------------------------
__global__ void __launch_bounds__(512) denom_kernel(const float* __restrict__ out)
{
    __shared__ float red[512];
    const int bh = blockIdx.x;
    const int b  = bh / HEADS;
    const int h  = bh % HEADS;
    const int g  = h >> 2;
    const int r  = 1 << g;
    const int off = (g == 2) ? 2 : g;

    const int tid   = threadIdx.x;
    const int d     = tid & 63;
    const int slice = tid >> 6;
    const int count = NTOK >> g;

    const float* p = out + ((long)b * NTOK + off) * ROWSTRIDE + h * 64 + d;
    float acc = 0.f;
    for (int t = slice; t < count; t += 8)
        acc += p[(long)t * r * ROWSTRIDE];

    red[tid] = acc;
    __syncthreads();
    if (slice == 0) {
        float sum = red[d];
        #pragma unroll
        for (int k = 1; k < 8; k++) sum += red[k * 64 + d];
        g_denom[bh * 64 + d] = sum;
    }
}

// ---------------------------------------------------------------------------
// Kernel 3: final normalize + zero uncovered positions.
// ---------------------------------------------------------------------------
__global__ void __launch_bounds__(256) norm_kernel(float* __restrict__ out)
{
    const long total = (long)2 * NTOK * HEADS * 64;
    long idx = (long)blockIdx.x * 256 + threadIdx.x;
    if (idx >= total) return;

    int  d = (int)(idx & 63);
    long t = idx >> 6;
    int  h = (int)(t % HEADS); t /= HEADS;
    int  n = (int)(t % NTOK);
    int  b = (int)(t / NTOK);

    int g   = h >> 2;
    int r   = 1 << g;
    int off = (g == 2) ? 2 : g;

    float v = 0.f;
    if ((n & (r - 1)) == off) {
        v = out[idx] / (g_denom[(b * HEADS + h) * 64 + d] * 3.0f);
    }
    out[idx] = v;
}

// ---------------------------------------------------------------------------
extern "C" void kernel_launch(void* const* d_in, const int* in_sizes, int n_in,
                              void* d_out, int out_size)
{
    const float* Q = (const float*)d_in[0];
    const float* K = (const float*)d_in[1];
    const float* V = (const float*)d_in[2];
    float* out = (float*)d_out;

    static int configured = 0;
    if (!configured) {
        cudaFuncSetAttribute(attn_kernel,
                             cudaFuncAttributeMaxDynamicSharedMemorySize, SMEM_BYTES);
        configured = 1;
    }

    attn_kernel<<<dim3(16, 56), 256, SMEM_BYTES>>>(Q, K, V, out);
    denom_kernel<<<2 * HEADS, 512>>>(out);

    const long total = (long)2 * NTOK * HEADS * 64;
    int blocks = (int)((total + 255) / 256);
    norm_kernel<<<blocks, 256>>>(out);
}

// round 13
// speedup vs baseline: 3.1244x; 1.4336x over previous
#include <cuda_runtime.h>
#include <cuda_fp16.h>
#include <cstdint>

#define NTOK 8192
#define HEADS 12
#define ROWSTRIDE 768   // HEADS*64 floats between consecutive tokens

__device__ float g_denom[2 * HEADS * 64];

// ---------------------------------------------------------------------------
// helpers
// ---------------------------------------------------------------------------
__device__ __forceinline__ float fast_exp2(float x) {
    float y; asm("ex2.approx.ftz.f32 %0, %1;" : "=f"(y) : "f"(x)); return y;
}
__device__ __forceinline__ uint32_t packh2(float lo, float hi) {
    uint32_t r;
    asm("cvt.rn.f16x2.f32 %0, %1, %2;" : "=r"(r) : "f"(hi), "f"(lo));
    return r;
}
__device__ __forceinline__ float2 unpackh2(uint32_t p) {
    __half2 h = *reinterpret_cast<__half2*>(&p);
    return __half22float2(h);
}
__device__ __forceinline__ uint32_t smem_u32(const void* p) {
    uint32_t a;
    asm("{ .reg .u64 t; cvta.to.shared.u64 t, %1; cvt.u32.u64 %0, t; }" : "=r"(a) : "l"(p));
    return a;
}
__device__ __forceinline__ void ldsm4(uint32_t r[4], uint32_t addr) {
    asm volatile("ldmatrix.sync.aligned.m8n8.x4.shared.b16 {%0,%1,%2,%3}, [%4];"
                 : "=r"(r[0]), "=r"(r[1]), "=r"(r[2]), "=r"(r[3]) : "r"(addr));
}
__device__ __forceinline__ void ldsm4t(uint32_t r[4], uint32_t addr) {
    asm volatile("ldmatrix.sync.aligned.m8n8.x4.trans.shared.b16 {%0,%1,%2,%3}, [%4];"
                 : "=r"(r[0]), "=r"(r[1]), "=r"(r[2]), "=r"(r[3]) : "r"(addr));
}
__device__ __forceinline__ void mma16816(float d[4], const uint32_t a[4],
                                         uint32_t b0, uint32_t b1, const float c[4]) {
    asm volatile(
        "mma.sync.aligned.m16n8k16.row.col.f32.f16.f16.f32 "
        "{%0,%1,%2,%3},{%4,%5,%6,%7},{%8,%9},{%10,%11,%12,%13};"
        : "=f"(d[0]), "=f"(d[1]), "=f"(d[2]), "=f"(d[3])
        : "r"(a[0]), "r"(a[1]), "r"(a[2]), "r"(a[3]), "r"(b0), "r"(b1),
          "f"(c[0]), "f"(c[1]), "f"(c[2]), "f"(c[3]));
}
__device__ __forceinline__ void cp_async16(uint32_t dst, const void* src) {
    asm volatile("cp.async.cg.shared.global [%0], [%1], 16;" :: "r"(dst), "l"(src));
}
#define CP_COMMIT() asm volatile("cp.async.commit_group;" ::: "memory")
#define CP_WAIT0()  asm volatile("cp.async.wait_group 0;" ::: "memory")

__device__ __forceinline__ float4 lds128f(uint32_t addr) {
    float4 v;
    asm volatile("ld.shared.v4.f32 {%0,%1,%2,%3}, [%4];"
                 : "=f"(v.x), "=f"(v.y), "=f"(v.z), "=f"(v.w) : "r"(addr));
    return v;
}

// swizzled byte offset of (row, 16B-chunk) in a [rows][64 half] tile (128B/row)
#define SWB(row, c8) (((uint32_t)(row) << 7) + ((((uint32_t)(c8)) ^ ((uint32_t)(row) & 7u)) << 4))

// smem layout (bytes from base)
#define O_RAWK 0
#define O_RAWV 32768
#define O_KH   65536
#define O_KL   81920
#define O_VH   98304
#define O_VL   114688
#define O_VU   131072
#define SMEM_BYTES 147456

#define C11 (1.0f / 2048.0f)
#define C22 (C11 * C11)

// ---------------------------------------------------------------------------
// Kernel 1: cp.async-pipelined scaled-split-fp16 mma.sync flash attention.
// CTA = (q-tile of 128 rows, job). 8 warps x 16 rows. BLOCK_N = 128.
// GEMM1: hh + (h*lo2 + lo2*h)*2^-11 + lo2*lo2*2^-22
// GEMM2: hh + (ph*vlo2 + plo2*vh + plo2*vlo_unscaled)*2^-11
// V consumed via ldmatrix.trans on row-major tiles (R2-verified mapping).
// ---------------------------------------------------------------------------
__global__ void __launch_bounds__(256) attn_kernel(
    const float* __restrict__ Q,
    const float* __restrict__ K,
    const float* __restrict__ V,
    float* __restrict__ out)
{
    extern __shared__ __align__(16) char smem_raw[];
    const uint32_t sb = smem_u32(smem_raw);

    const int tid  = threadIdx.x;
    const int wid  = tid >> 5;
    const int lane = tid & 31;

    // ---- decode job ----
    const int job = blockIdx.y;
    int g, b, seg, hl;
    if (job < 32)      { g = 0; hl = job & 3;  seg = (job >> 2) & 3; b = job >> 4; }
    else if (job < 48) { int l = job - 32; g = 1; hl = l & 3; seg = (l >> 2) & 1; b = l >> 3; }
    else               { int l = job - 48; g = 2; hl = l & 3; seg = 0;            b = l >> 2; }
    const int r   = 1 << g;
    const int s   = 2048 << g;
    const int off = (g == 2) ? 2 : g;
    const int h   = g * 4 + hl;
    const long rstride = (long)r * ROWSTRIDE;
    const long segbase = ((long)b * NTOK + (long)seg * s + off) * ROWSTRIDE + h * 64;
    const long qbase   = segbase + (long)blockIdx.x * 128 * rstride;

    // ---- prefetch raw K/V tile 0 (flies during Q staging) ----
    {
        const float* kb = K + segbase;
        const float* vb = V + segbase;
        #pragma unroll
        for (int i = 0; i < 8; i++) {
            int c = tid + (i << 8);
            int row = c >> 4, sub = c & 15;
            cp_async16(sb + O_RAWK + (uint32_t)c * 16, kb + (long)row * rstride + (sub << 2));
        }
        #pragma unroll
        for (int i = 0; i < 8; i++) {
            int c = tid + (i << 8);
            int row = c >> 4, sub = c & 15;
            cp_async16(sb + O_RAWV + (uint32_t)c * 16, vb + (long)row * rstride + (sub << 2));
        }
        CP_COMMIT();
    }

    // ---- stage Q (pre-scaled): hi into KH, residual*2048 into KL ----
    const float qs = 0.125f * 1.4426950408889634f;
    #pragma unroll
    for (int i = 0; i < 8; i++) {
        int linear = tid + (i << 8);
        int row = linear >> 4, f4 = linear & 15;
        float4 v = *(const float4*)(Q + qbase + (long)row * rstride + (f4 << 2));
        v.x *= qs; v.y *= qs; v.z *= qs; v.w *= qs;
        uint32_t h0 = packh2(v.x, v.y), h1 = packh2(v.z, v.w);
        float2 f0 = unpackh2(h0), f1 = unpackh2(h1);
        uint32_t l0_ = packh2((v.x - f0.x) * 2048.f, (v.y - f0.y) * 2048.f);
        uint32_t l1_ = packh2((v.z - f1.x) * 2048.f, (v.w - f1.y) * 2048.f);
        uint32_t o8 = SWB(row, f4 >> 1) + ((uint32_t)(f4 & 1) << 3);
        asm volatile("st.shared.v2.b32 [%0], {%1,%2};" :: "r"(sb + O_KH + o8), "r"(h0), "r"(h1));
        asm volatile("st.shared.v2.b32 [%0], {%1,%2};" :: "r"(sb + O_KL + o8), "r"(l0_), "r"(l1_));
    }
    __syncthreads();

    uint32_t qfh[4][4], qfl[4][4];
    {
        uint32_t row = (uint32_t)(wid * 16 + (lane & 15));
        #pragma unroll
        for (int ks = 0; ks < 4; ks++) {
            uint32_t chunk = (uint32_t)(lane >> 4) + ((uint32_t)ks << 1);
            ldsm4(qfh[ks], sb + O_KH + SWB(row, chunk));
            ldsm4(qfl[ks], sb + O_KL + SWB(row, chunk));
        }
    }

    float oacc[8][4];
    #pragma unroll
    for (int i = 0; i < 8; i++)
        #pragma unroll
        for (int e = 0; e < 4; e++) oacc[i][e] = 0.f;
    float lr0 = 0.f, lr1 = 0.f;

    for (int kt = 0; kt < 16; kt++) {
        __syncthreads();              // prev MMA/ldsm done: fp16 buffers free
        CP_WAIT0();
        __syncthreads();              // raw(kt) visible CTA-wide

        // ---- convert raw K -> KH/KL ----
        #pragma unroll
        for (int i = 0; i < 8; i++) {
            int c = tid + (i << 8);
            int row = c >> 4, f4 = c & 15;
            float4 v = lds128f(sb + O_RAWK + (uint32_t)c * 16);
            uint32_t h0 = packh2(v.x, v.y), h1 = packh2(v.z, v.w);
            float2 f0 = unpackh2(h0), f1 = unpackh2(h1);
            uint32_t l0_ = packh2((v.x - f0.x) * 2048.f, (v.y - f0.y) * 2048.f);
            uint32_t l1_ = packh2((v.z - f1.x) * 2048.f, (v.w - f1.y) * 2048.f);
            uint32_t o8 = SWB(row, f4 >> 1) + ((uint32_t)(f4 & 1) << 3);
            asm volatile("st.shared.v2.b32 [%0], {%1,%2};" :: "r"(sb + O_KH + o8), "r"(h0), "r"(h1));
            asm volatile("st.shared.v2.b32 [%0], {%1,%2};" :: "r"(sb + O_KL + o8), "r"(l0_), "r"(l1_));
        }
        // ---- convert raw V -> VH / VL(*2048) / VU (row-major, swizzled) ----
        #pragma unroll
        for (int i = 0; i < 8; i++) {
            int c = tid + (i << 8);
            int row = c >> 4, f4 = c & 15;
            float4 v = lds128f(sb + O_RAWV + (uint32_t)c * 16);
            uint32_t h0 = packh2(v.x, v.y), h1 = packh2(v.z, v.w);
            float2 f0 = unpackh2(h0), f1 = unpackh2(h1);
            float r0 = v.x - f0.x, r1 = v.y - f0.y, r2 = v.z - f1.x, r3 = v.w - f1.y;
            uint32_t sl0 = packh2(r0 * 2048.f, r1 * 2048.f);
            uint32_t sl1 = packh2(r2 * 2048.f, r3 * 2048.f);
            uint32_t su0 = packh2(r0, r1);
            uint32_t su1 = packh2(r2, r3);
            uint32_t o8 = SWB(row, f4 >> 1) + ((uint32_t)(f4 & 1) << 3);
            asm volatile("st.shared.v2.b32 [%0], {%1,%2};" :: "r"(sb + O_VH + o8), "r"(h0), "r"(h1));
            asm volatile("st.shared.v2.b32 [%0], {%1,%2};" :: "r"(sb + O_VL + o8), "r"(sl0), "r"(sl1));
            asm volatile("st.shared.v2.b32 [%0], {%1,%2};" :: "r"(sb + O_VU + o8), "r"(su0), "r"(su1));
        }

        // ---- prefetch raw tile kt+1 (same thread->chunk map: no extra sync) ----
        if (kt < 15) {
            const float* kb = K + segbase + (long)((kt + 1) * 128) * rstride;
            const float* vb = V + segbase + (long)((kt + 1) * 128) * rstride;
            #pragma unroll
            for (int i = 0; i < 8; i++) {
                int c = tid + (i << 8);
                int row = c >> 4, sub = c & 15;
                cp_async16(sb + O_RAWK + (uint32_t)c * 16, kb + (long)row * rstride + (sub << 2));
            }
            #pragma unroll
            for (int i = 0; i < 8; i++) {
                int c = tid + (i << 8);
                int row = c >> 4, sub = c & 15;
                cp_async16(sb + O_RAWV + (uint32_t)c * 16, vb + (long)row * rstride + (sub << 2));
            }
            CP_COMMIT();
        }
        __syncthreads();              // fp16 buffers ready

        // ---- fused per 16-col block j: GEMM1 -> softmax -> GEMM2 ----
        float ocor[8][4];
        #pragma unroll
        for (int i = 0; i < 8; i++)
            #pragma unroll
            for (int e = 0; e < 4; e++) ocor[i][e] = 0.f;

        #pragma unroll
        for (int j = 0; j < 8; j++) {
            float a0[2][4], a1[2][4], a2[2][4];
            #pragma unroll
            for (int hh = 0; hh < 2; hh++)
                #pragma unroll
                for (int e = 0; e < 4; e++) { a0[hh][e] = 0.f; a1[hh][e] = 0.f; a2[hh][e] = 0.f; }

            uint32_t row = ((uint32_t)j << 4) + (uint32_t)(lane & 15);
            #pragma unroll
            for (int ks = 0; ks < 4; ks++) {
                uint32_t chunk = (uint32_t)(lane >> 4) + ((uint32_t)ks << 1);
                uint32_t kh[4], kl[4];
                ldsm4(kh, sb + O_KH + SWB(row, chunk));
                ldsm4(kl, sb + O_KL + SWB(row, chunk));
                mma16816(a0[0], qfh[ks], kh[0], kh[2], a0[0]);
                mma16816(a0[1], qfh[ks], kh[1], kh[3], a0[1]);
                mma16816(a1[0], qfh[ks], kl[0], kl[2], a1[0]);
                mma16816(a1[1], qfh[ks], kl[1], kl[3], a1[1]);
                mma16816(a1[0], qfl[ks], kh[0], kh[2], a1[0]);
                mma16816(a1[1], qfl[ks], kh[1], kh[3], a1[1]);
                mma16816(a2[0], qfl[ks], kl[0], kl[2], a2[0]);
                mma16816(a2[1], qfl[ks], kl[1], kl[3], a2[1]);
            }

            uint32_t pfh[4], pfl[4];
            {
                float s0 = a0[0][0] + a1[0][0] * C11 + a2[0][0] * C22;
                float s1 = a0[0][1] + a1[0][1] * C11 + a2[0][1] * C22;
                float s2 = a0[0][2] + a1[0][2] * C11 + a2[0][2] * C22;
                float s3 = a0[0][3] + a1[0][3] * C11 + a2[0][3] * C22;
                float s4 = a0[1][0] + a1[1][0] * C11 + a2[1][0] * C22;
                float s5 = a0[1][1] + a1[1][1] * C11 + a2[1][1] * C22;
                float s6 = a0[1][2] + a1[1][2] * C11 + a2[1][2] * C22;
                float s7 = a0[1][3] + a1[1][3] * C11 + a2[1][3] * C22;
                float p0 = fast_exp2(s0), p1 = fast_exp2(s1);
                float p2 = fast_exp2(s2), p3 = fast_exp2(s3);
                float p4 = fast_exp2(s4), p5 = fast_exp2(s5);
                float p6 = fast_exp2(s6), p7 = fast_exp2(s7);
                lr0 += (p0 + p1) + (p4 + p5);
                lr1 += (p2 + p3) + (p6 + p7);
                pfh[0] = packh2(p0, p1);
                pfh[1] = packh2(p2, p3);
                pfh[2] = packh2(p4, p5);
                pfh[3] = packh2(p6, p7);
                float2 f;
                f = unpackh2(pfh[0]); pfl[0] = packh2((p0 - f.x) * 2048.f, (p1 - f.y) * 2048.f);
                f = unpackh2(pfh[1]); pfl[1] = packh2((p2 - f.x) * 2048.f, (p3 - f.y) * 2048.f);
                f = unpackh2(pfh[2]); pfl[2] = packh2((p4 - f.x) * 2048.f, (p5 - f.y) * 2048.f);
                f = unpackh2(pfh[3]); pfl[3] = packh2((p6 - f.x) * 2048.f, (p7 - f.y) * 2048.f);
            }

            // GEMM2: ldmatrix.trans on row-major V tiles (R2-verified pattern)
            uint32_t jr = ((uint32_t)j << 4) + (uint32_t)(lane & 7) + ((((uint32_t)lane >> 3) & 1u) << 3);
            #pragma unroll
            for (int dp = 0; dp < 4; dp++) {
                uint32_t chunk = (uint32_t)(lane >> 4) + ((uint32_t)dp << 1);
                uint32_t vh[4], vl[4], vu[4];
                ldsm4t(vh, sb + O_VH + SWB(jr, chunk));
                ldsm4t(vl, sb + O_VL + SWB(jr, chunk));
                ldsm4t(vu, sb + O_VU + SWB(jr, chunk));
                mma16816(oacc[2*dp],   pfh, vh[0], vh[1], oacc[2*dp]);
                mma16816(oacc[2*dp+1], pfh, vh[2], vh[3], oacc[2*dp+1]);
                mma16816(ocor[2*dp],   pfh, vl[0], vl[1], ocor[2*dp]);
                mma16816(ocor[2*dp+1], pfh, vl[2], vl[3], ocor[2*dp+1]);
                mma16816(ocor[2*dp],   pfl, vh[0], vh[1], ocor[2*dp]);
                mma16816(ocor[2*dp+1], pfl, vh[2], vh[3], ocor[2*dp+1]);
                mma16816(ocor[2*dp],   pfl, vu[0], vu[1], ocor[2*dp]);
                mma16816(ocor[2*dp+1], pfl, vu[2], vu[3], ocor[2*dp+1]);
            }
        }
        // fold correction into main accumulator
        #pragma unroll
        for (int i = 0; i < 8; i++)
            #pragma unroll
            for (int e = 0; e < 4; e++)
                oacc[i][e] = fmaf(ocor[i][e], C11, oacc[i][e]);
    }

    // ---- epilogue: reduce l across quad, normalize, write ----
    lr0 += __shfl_xor_sync(0xffffffffu, lr0, 1);
    lr0 += __shfl_xor_sync(0xffffffffu, lr0, 2);
    lr1 += __shfl_xor_sync(0xffffffffu, lr1, 1);
    lr1 += __shfl_xor_sync(0xffffffffu, lr1, 2);
    const float inv0 = 1.f / lr0;
    const float inv1 = 1.f / lr1;

    const int gq = lane >> 2, t4 = lane & 3;
    float* r0p = out + qbase + (long)(wid * 16 + gq) * rstride;
    float* r1p = out + qbase + (long)(wid * 16 + gq + 8) * rstride;
    #pragma unroll
    for (int dt = 0; dt < 8; dt++) {
        float2 w0 = make_float2(oacc[dt][0] * inv0, oacc[dt][1] * inv0);
        float2 w1 = make_float2(oacc[dt][2] * inv1, oacc[dt][3] * inv1);
        *(float2*)(r0p + dt * 8 + 2 * t4) = w0;
        *(float2*)(r1p + dt * 8 + 2 * t4) = w1;
    }
}

// ---------------------------------------------------------------------------
// Kernel 2: deterministic per-(b,h,d) sum over covered positions.
// ---------------------------------------------------------------------------
__global__ void __launch_bounds__(512) denom_kernel(const float* __restrict__ out)
{
    __shared__ float red[512];
    const int bh = blockIdx.x;
    const int b  = bh / HEADS;
    const int h  = bh % HEADS;
    const int g  = h >> 2;
    const int r  = 1 << g;
    const int off = (g == 2) ? 2 : g;

    const int tid   = threadIdx.x;
    const int d     = tid & 63;
    const int slice = tid >> 6;
    const int count = NTOK >> g;

    const float* p = out + ((long)b * NTOK + off) * ROWSTRIDE + h * 64 + d;
    float acc = 0.f;
    for (int t = slice; t < count; t += 8)
        acc += p[(long)t * r * ROWSTRIDE];

    red[tid] = acc;
    __syncthreads();
    if (slice == 0) {
        float sum = red[d];
        #pragma unroll
        for (int k = 1; k < 8; k++) sum += red[k * 64 + d];
        g_denom[bh * 64 + d] = sum;
    }
}

// ---------------------------------------------------------------------------
// Kernel 3: final normalize + zero uncovered positions (float4).
// ---------------------------------------------------------------------------
__global__ void __launch_bounds__(256) norm_kernel(float4* __restrict__ out4)
{
    const long total4 = (long)2 * NTOK * HEADS * 16;
    long i4 = (long)blockIdx.x * 256 + threadIdx.x;
    if (i4 >= total4) return;

    int  dq = (int)(i4 & 15);
    long t = i4 >> 4;
    int  h = (int)(t % HEADS); t /= HEADS;
    int  n = (int)(t % NTOK);
    int  b = (int)(t / NTOK);

    int g   = h >> 2;
    int r   = 1 << g;
    int off = (g == 2) ? 2 : g;

    float4 v = make_float4(0.f, 0.f, 0.f, 0.f);
    if ((n & (r - 1)) == off) {
        float4 x = out4[i4];
        const float* dn = g_denom + (b * HEADS + h) * 64 + dq * 4;
        v.x = x.x / (dn[0] * 3.0f);
        v.y = x.y / (dn[1] * 3.0f);
        v.z = x.z / (dn[2] * 3.0f);
        v.w = x.w / (dn[3] * 3.0f);
    }
    out4[i4] = v;
}

// ---------------------------------------------------------------------------
extern "C" void kernel_launch(void* const* d_in, const int* in_sizes, int n_in,
                              void* d_out, int out_size)
{
    const float* Q = (const float*)d_in[0];
    const float* K = (const float*)d_in[1];
    const float* V = (const float*)d_in[2];
    float* out = (float*)d_out;

    static int configured = 0;
    if (!configured) {
        cudaFuncSetAttribute(attn_kernel,
                             cudaFuncAttributeMaxDynamicSharedMemorySize, SMEM_BYTES);
        configured = 1;
    }

    attn_kernel<<<dim3(16, 56), 256, SMEM_BYTES>>>(Q, K, V, out);
    denom_kernel<<<2 * HEADS, 512>>>(out);

    const long total4 = (long)2 * NTOK * HEADS * 16;
    int blocks = (int)((total4 + 255) / 256);
    norm_kernel<<<blocks, 256>>>((float4*)out);
}

// round 14
// speedup vs baseline: 3.3090x; 1.0591x over previous
#include <cuda_runtime.h>
#include <cuda_fp16.h>
#include <cstdint>

#define NTOK 8192
#define HEADS 12
#define ROWSTRIDE 768   // HEADS*64 floats between consecutive tokens

__device__ float g_denom[2 * HEADS * 64];
__device__ float g_partial[2 * HEADS * 8 * 64];

// ---------------------------------------------------------------------------
// helpers
// ---------------------------------------------------------------------------
__device__ __forceinline__ float fast_exp2(float x) {
    float y; asm("ex2.approx.ftz.f32 %0, %1;" : "=f"(y) : "f"(x)); return y;
}
__device__ __forceinline__ uint32_t packh2(float lo, float hi) {
    uint32_t r;
    asm("cvt.rn.f16x2.f32 %0, %1, %2;" : "=r"(r) : "f"(hi), "f"(lo));
    return r;
}
__device__ __forceinline__ float2 unpackh2(uint32_t p) {
    __half2 h = *reinterpret_cast<__half2*>(&p);
    return __half22float2(h);
}
__device__ __forceinline__ uint32_t smem_u32(const void* p) {
    uint32_t a;
    asm("{ .reg .u64 t; cvta.to.shared.u64 t, %1; cvt.u32.u64 %0, t; }" : "=r"(a) : "l"(p));
    return a;
}
__device__ __forceinline__ void ldsm4(uint32_t r[4], uint32_t addr) {
    asm volatile("ldmatrix.sync.aligned.m8n8.x4.shared.b16 {%0,%1,%2,%3}, [%4];"
                 : "=r"(r[0]), "=r"(r[1]), "=r"(r[2]), "=r"(r[3]) : "r"(addr));
}
__device__ __forceinline__ void ldsm4t(uint32_t r[4], uint32_t addr) {
    asm volatile("ldmatrix.sync.aligned.m8n8.x4.trans.shared.b16 {%0,%1,%2,%3}, [%4];"
                 : "=r"(r[0]), "=r"(r[1]), "=r"(r[2]), "=r"(r[3]) : "r"(addr));
}
__device__ __forceinline__ void mma16816(float d[4], const uint32_t a[4],
                                         uint32_t b0, uint32_t b1, const float c[4]) {
    asm volatile(
        "mma.sync.aligned.m16n8k16.row.col.f32.f16.f16.f32 "
        "{%0,%1,%2,%3},{%4,%5,%6,%7},{%8,%9},{%10,%11,%12,%13};"
        : "=f"(d[0]), "=f"(d[1]), "=f"(d[2]), "=f"(d[3])
        : "r"(a[0]), "r"(a[1]), "r"(a[2]), "r"(a[3]), "r"(b0), "r"(b1),
          "f"(c[0]), "f"(c[1]), "f"(c[2]), "f"(c[3]));
}
__device__ __forceinline__ void cp_async16(uint32_t dst, const void* src) {
    asm volatile("cp.async.cg.shared.global [%0], [%1], 16;" :: "r"(dst), "l"(src));
}
#define CP_COMMIT() asm volatile("cp.async.commit_group;" ::: "memory")
#define CP_WAIT(n)  asm volatile("cp.async.wait_group %0;" :: "n"(n) : "memory")

__device__ __forceinline__ float4 lds128f(uint32_t addr) {
    float4 v;
    asm volatile("ld.shared.v4.f32 {%0,%1,%2,%3}, [%4];"
                 : "=f"(v.x), "=f"(v.y), "=f"(v.z), "=f"(v.w) : "r"(addr));
    return v;
}

// swizzled byte offset of (row, 16B-chunk) in a [rows][64 half] tile (128B/row)
#define SWB(row, c8) (((uint32_t)(row) << 7) + ((((uint32_t)(c8)) ^ ((uint32_t)(row) & 7u)) << 4))

// smem layout
#define O_RAWK 0            // 32 KB raw fp32 K tile
#define O_RAWV 32768        // 32 KB raw fp32 V tile
#define O_BUF  65536        // 2 x 64 KB fp16 buffer sets
#define B_KH 0
#define B_KL 16384
#define B_VH 32768
#define B_VL 49152
#define SMEM_BYTES (65536 + 2 * 65536)   // 192 KB

#define C11 (1.0f / 2048.0f)
#define C22 (C11 * C11)

// convert raw chunk c (K and V) into fp16 buffer set dst
__device__ __forceinline__ void convert_chunk(uint32_t sb, uint32_t dst, int c) {
    const int row = c >> 4, f4 = c & 15;
    const uint32_t o8 = SWB(row, f4 >> 1) + ((uint32_t)(f4 & 1) << 3);
    {
        float4 v = lds128f(sb + O_RAWK + (uint32_t)c * 16);
        uint32_t h0 = packh2(v.x, v.y), h1 = packh2(v.z, v.w);
        float2 f0 = unpackh2(h0), f1 = unpackh2(h1);
        uint32_t l0_ = packh2((v.x - f0.x) * 2048.f, (v.y - f0.y) * 2048.f);
        uint32_t l1_ = packh2((v.z - f1.x) * 2048.f, (v.w - f1.y) * 2048.f);
        asm volatile("st.shared.v2.b32 [%0], {%1,%2};" :: "r"(dst + B_KH + o8), "r"(h0), "r"(h1));
        asm volatile("st.shared.v2.b32 [%0], {%1,%2};" :: "r"(dst + B_KL + o8), "r"(l0_), "r"(l1_));
    }
    {
        float4 v = lds128f(sb + O_RAWV + (uint32_t)c * 16);
        uint32_t h0 = packh2(v.x, v.y), h1 = packh2(v.z, v.w);
        float2 f0 = unpackh2(h0), f1 = unpackh2(h1);
        uint32_t l0_ = packh2((v.x - f0.x) * 2048.f, (v.y - f0.y) * 2048.f);
        uint32_t l1_ = packh2((v.z - f1.x) * 2048.f, (v.w - f1.y) * 2048.f);
        asm volatile("st.shared.v2.b32 [%0], {%1,%2};" :: "r"(dst + B_VH + o8), "r"(h0), "r"(h1));
        asm volatile("st.shared.v2.b32 [%0], {%1,%2};" :: "r"(dst + B_VL + o8), "r"(l0_), "r"(l1_));
    }
}

// issue cp.async for chunk c of (K,V) tile at kb/vb; one commit group
__device__ __forceinline__ void issue_chunk(uint32_t sb, int c,
                                            const float* kb, const float* vb,
                                            long rstride) {
    const int row = c >> 4, f4 = c & 15;
    cp_async16(sb + O_RAWK + (uint32_t)c * 16, kb + (long)row * rstride + (f4 << 2));
    cp_async16(sb + O_RAWV + (uint32_t)c * 16, vb + (long)row * rstride + (f4 << 2));
    CP_COMMIT();
}

// ---------------------------------------------------------------------------
// Kernel 1: fully-pipelined scaled-split-fp16 mma.sync flash attention.
// CTA = (q-tile of 128 rows, job). 8 warps x 16 rows. BLOCK_N = 128.
// Convert of tile kt+1 + cp.async refill of tile kt+2 interleaved into the
// MMA j-loop of tile kt (double-buffered fp16 tiles, per-chunk async groups).
// ---------------------------------------------------------------------------
__global__ void __launch_bounds__(256) attn_kernel(
    const float* __restrict__ Q,
    const float* __restrict__ K,
    const float* __restrict__ V,
    float* __restrict__ out)
{
    extern __shared__ __align__(16) char smem_raw[];
    const uint32_t sb = smem_u32(smem_raw);
    const uint32_t buf0 = sb + O_BUF;
    const uint32_t buf1 = sb + O_BUF + 65536u;

    const int tid  = threadIdx.x;
    const int wid  = tid >> 5;
    const int lane = tid & 31;

    // ---- decode job ----
    const int job = blockIdx.y;
    int g, b, seg, hl;
    if (job < 32)      { g = 0; hl = job & 3;  seg = (job >> 2) & 3; b = job >> 4; }
    else if (job < 48) { int l = job - 32; g = 1; hl = l & 3; seg = (l >> 2) & 1; b = l >> 3; }
    else               { int l = job - 48; g = 2; hl = l & 3; seg = 0;            b = l >> 2; }
    const int r   = 1 << g;
    const int s   = 2048 << g;
    const int off = (g == 2) ? 2 : g;
    const int h   = g * 4 + hl;
    const long rstride = (long)r * ROWSTRIDE;
    const long segbase = ((long)b * NTOK + (long)seg * s + off) * ROWSTRIDE + h * 64;
    const long qbase   = segbase + (long)blockIdx.x * 128 * rstride;

    // ---- prologue: cp.async raw tile 0 (single group) ----
    {
        const float* kb = K + segbase;
        const float* vb = V + segbase;
        #pragma unroll
        for (int i = 0; i < 8; i++) {
            int c = tid + (i << 8);
            int row = c >> 4, f4 = c & 15;
            cp_async16(sb + O_RAWK + (uint32_t)c * 16, kb + (long)row * rstride + (f4 << 2));
            cp_async16(sb + O_RAWV + (uint32_t)c * 16, vb + (long)row * rstride + (f4 << 2));
        }
        CP_COMMIT();
    }

    // ---- stage Q (pre-scaled) into buf0.KH/KL, extract fragments ----
    const float qs = 0.125f * 1.4426950408889634f;
    #pragma unroll
    for (int i = 0; i < 8; i++) {
        int linear = tid + (i << 8);
        int row = linear >> 4, f4 = linear & 15;
        float4 v = *(const float4*)(Q + qbase + (long)row * rstride + (f4 << 2));
        v.x *= qs; v.y *= qs; v.z *= qs; v.w *= qs;
        uint32_t h0 = packh2(v.x, v.y), h1 = packh2(v.z, v.w);
        float2 f0 = unpackh2(h0), f1 = unpackh2(h1);
        uint32_t l0_ = packh2((v.x - f0.x) * 2048.f, (v.y - f0.y) * 2048.f);
        uint32_t l1_ = packh2((v.z - f1.x) * 2048.f, (v.w - f1.y) * 2048.f);
        uint32_t o8 = SWB(row, f4 >> 1) + ((uint32_t)(f4 & 1) << 3);
        asm volatile("st.shared.v2.b32 [%0], {%1,%2};" :: "r"(buf0 + B_KH + o8), "r"(h0), "r"(h1));
        asm volatile("st.shared.v2.b32 [%0], {%1,%2};" :: "r"(buf0 + B_KL + o8), "r"(l0_), "r"(l1_));
    }
    __syncthreads();

    uint32_t qfh[4][4], qfl[4][4];
    {
        uint32_t row = (uint32_t)(wid * 16 + (lane & 15));
        #pragma unroll
        for (int ks = 0; ks < 4; ks++) {
            uint32_t chunk = (uint32_t)(lane >> 4) + ((uint32_t)ks << 1);
            ldsm4(qfh[ks], buf0 + B_KH + SWB(row, chunk));
            ldsm4(qfl[ks], buf0 + B_KL + SWB(row, chunk));
        }
    }
    __syncthreads();   // all warps read Q before convert overwrites buf0

    // ---- wait raw tile0 (per-thread chunks), convert to buf0, issue tile1 ----
    CP_WAIT(0);
    {
        const float* kb = K + segbase + (long)128 * rstride;
        const float* vb = V + segbase + (long)128 * rstride;
        #pragma unroll
        for (int j = 0; j < 8; j++) {
            int c = tid + (j << 8);
            convert_chunk(sb, buf0, c);
            issue_chunk(sb, c, kb, vb, rstride);   // tile1, one group per chunk
        }
    }
    __syncthreads();   // buf0 ready

    float oacc[8][4];
    #pragma unroll
    for (int i = 0; i < 8; i++)
        #pragma unroll
        for (int e = 0; e < 4; e++) oacc[i][e] = 0.f;
    float lr0 = 0.f, lr1 = 0.f;

    for (int kt = 0; kt < 16; kt++) {
        const uint32_t cur = (kt & 1) ? buf1 : buf0;
        const uint32_t nxt = (kt & 1) ? buf0 : buf1;
        int nt = (kt + 2 < 16) ? (kt + 2) : 15;
        const float* kb2 = K + segbase + (long)(nt * 128) * rstride;
        const float* vb2 = V + segbase + (long)(nt * 128) * rstride;
        const bool doconv = (kt < 15);

        float ocor[8][4];
        #pragma unroll
        for (int i = 0; i < 8; i++)
            #pragma unroll
            for (int e = 0; e < 4; e++) ocor[i][e] = 0.f;

        #pragma unroll
        for (int j = 0; j < 8; j++) {
            // ---- GEMM1 block j: hh + mid + ll accumulators ----
            float a0[2][4], a1[2][4], a2[2][4];
            #pragma unroll
            for (int hh = 0; hh < 2; hh++)
                #pragma unroll
                for (int e = 0; e < 4; e++) { a0[hh][e] = 0.f; a1[hh][e] = 0.f; a2[hh][e] = 0.f; }

            uint32_t row = ((uint32_t)j << 4) + (uint32_t)(lane & 15);
            #pragma unroll
            for (int ks = 0; ks < 4; ks++) {
                uint32_t chunk = (uint32_t)(lane >> 4) + ((uint32_t)ks << 1);
                uint32_t kh[4], kl[4];
                ldsm4(kh, cur + B_KH + SWB(row, chunk));
                ldsm4(kl, cur + B_KL + SWB(row, chunk));
                mma16816(a0[0], qfh[ks], kh[0], kh[2], a0[0]);
                mma16816(a0[1], qfh[ks], kh[1], kh[3], a0[1]);
                mma16816(a1[0], qfh[ks], kl[0], kl[2], a1[0]);
                mma16816(a1[1], qfh[ks], kl[1], kl[3], a1[1]);
                mma16816(a1[0], qfl[ks], kh[0], kh[2], a1[0]);
                mma16816(a1[1], qfl[ks], kh[1], kh[3], a1[1]);
                mma16816(a2[0], qfl[ks], kl[0], kl[2], a2[0]);
                mma16816(a2[1], qfl[ks], kl[1], kl[3], a2[1]);
            }

            // ---- softmax: P hi / lo2 / lo-unscaled fragments ----
            uint32_t pfh[4], pfl[4], pfu[4];
            {
                float s0 = a0[0][0] + a1[0][0] * C11 + a2[0][0] * C22;
                float s1 = a0[0][1] + a1[0][1] * C11 + a2[0][1] * C22;
                float s2 = a0[0][2] + a1[0][2] * C11 + a2[0][2] * C22;
                float s3 = a0[0][3] + a1[0][3] * C11 + a2[0][3] * C22;
                float s4 = a0[1][0] + a1[1][0] * C11 + a2[1][0] * C22;
                float s5 = a0[1][1] + a1[1][1] * C11 + a2[1][1] * C22;
                float s6 = a0[1][2] + a1[1][2] * C11 + a2[1][2] * C22;
                float s7 = a0[1][3] + a1[1][3] * C11 + a2[1][3] * C22;
                float p0 = fast_exp2(s0), p1 = fast_exp2(s1);
                float p2 = fast_exp2(s2), p3 = fast_exp2(s3);
                float p4 = fast_exp2(s4), p5 = fast_exp2(s5);
                float p6 = fast_exp2(s6), p7 = fast_exp2(s7);
                lr0 += (p0 + p1) + (p4 + p5);
                lr1 += (p2 + p3) + (p6 + p7);
                pfh[0] = packh2(p0, p1);
                pfh[1] = packh2(p2, p3);
                pfh[2] = packh2(p4, p5);
                pfh[3] = packh2(p6, p7);
                float2 f;
                float d0, d1;
                f = unpackh2(pfh[0]); d0 = p0 - f.x; d1 = p1 - f.y;
                pfl[0] = packh2(d0 * 2048.f, d1 * 2048.f); pfu[0] = packh2(d0, d1);
                f = unpackh2(pfh[1]); d0 = p2 - f.x; d1 = p3 - f.y;
                pfl[1] = packh2(d0 * 2048.f, d1 * 2048.f); pfu[1] = packh2(d0, d1);
                f = unpackh2(pfh[2]); d0 = p4 - f.x; d1 = p5 - f.y;
                pfl[2] = packh2(d0 * 2048.f, d1 * 2048.f); pfu[2] = packh2(d0, d1);
                f = unpackh2(pfh[3]); d0 = p6 - f.x; d1 = p7 - f.y;
                pfl[3] = packh2(d0 * 2048.f, d1 * 2048.f); pfu[3] = packh2(d0, d1);
            }

            // ---- GEMM2: ldmatrix.trans on row-major V (hi + corrections) ----
            uint32_t jr = ((uint32_t)j << 4) + (uint32_t)(lane & 7) + ((((uint32_t)lane >> 3) & 1u) << 3);
            #pragma unroll
            for (int dp = 0; dp < 4; dp++) {
                uint32_t chunk = (uint32_t)(lane >> 4) + ((uint32_t)dp << 1);
                uint32_t vh[4], vl[4];
                ldsm4t(vh, cur + B_VH + SWB(jr, chunk));
                ldsm4t(vl, cur + B_VL + SWB(jr, chunk));
                mma16816(oacc[2*dp],   pfh, vh[0], vh[1], oacc[2*dp]);
                mma16816(oacc[2*dp+1], pfh, vh[2], vh[3], oacc[2*dp+1]);
                mma16816(ocor[2*dp],   pfh, vl[0], vl[1], ocor[2*dp]);
                mma16816(ocor[2*dp+1], pfh, vl[2], vl[3], ocor[2*dp+1]);
                mma16816(ocor[2*dp],   pfl, vh[0], vh[1], ocor[2*dp]);
                mma16816(ocor[2*dp+1], pfl, vh[2], vh[3], ocor[2*dp+1]);
                mma16816(ocor[2*dp],   pfu, vl[0], vl[1], ocor[2*dp]);   // == pfl*vu
                mma16816(ocor[2*dp+1], pfu, vl[2], vl[3], ocor[2*dp+1]);
            }

            // ---- interleaved: convert chunk j of tile kt+1, refill tile kt+2 ----
            if (doconv) {
                CP_WAIT(7);                       // retire oldest group = chunk j of tile kt+1
                int c = tid + (j << 8);
                convert_chunk(sb, nxt, c);
                issue_chunk(sb, c, kb2, vb2, rstride);
            }
        }

        // fold correction into main accumulator (per tile, as in R12/R13)
        #pragma unroll
        for (int i = 0; i < 8; i++)
            #pragma unroll
            for (int e = 0; e < 4; e++)
                oacc[i][e] = fmaf(ocor[i][e], C11, oacc[i][e]);

        __syncthreads();   // all warps done with cur before next iter overwrites it
    }
    CP_WAIT(0);            // retire trailing dummy groups before exit

    // ---- epilogue: reduce l across quad, normalize, write ----
    lr0 += __shfl_xor_sync(0xffffffffu, lr0, 1);
    lr0 += __shfl_xor_sync(0xffffffffu, lr0, 2);
    lr1 += __shfl_xor_sync(0xffffffffu, lr1, 1);
    lr1 += __shfl_xor_sync(0xffffffffu, lr1, 2);
    const float inv0 = 1.f / lr0;
    const float inv1 = 1.f / lr1;

    const int gq = lane >> 2, t4 = lane & 3;
    float* r0p = out + qbase + (long)(wid * 16 + gq) * rstride;
    float* r1p = out + qbase + (long)(wid * 16 + gq + 8) * rstride;
    #pragma unroll
    for (int dt = 0; dt < 8; dt++) {
        float2 w0 = make_float2(oacc[dt][0] * inv0, oacc[dt][1] * inv0);
        float2 w1 = make_float2(oacc[dt][2] * inv1, oacc[dt][3] * inv1);
        *(float2*)(r0p + dt * 8 + 2 * t4) = w0;
        *(float2*)(r1p + dt * 8 + 2 * t4) = w1;
    }
}

// ---------------------------------------------------------------------------
// Kernel 2a: per-(b,h) partial sums over covered positions (8 parts).
// ---------------------------------------------------------------------------
__global__ void __launch_bounds__(512) denom_partial(const float* __restrict__ out)
{
    __shared__ float red[512];
    const int bh   = blockIdx.x;      // 0..23
    const int part = blockIdx.y;      // 0..7
    const int b  = bh / HEADS;
    const int h  = bh % HEADS;
    const int g  = h >> 2;
    const int r  = 1 << g;
    const int off = (g == 2) ? 2 : g;

    const int tid   = threadIdx.x;
    const int d     = tid & 63;
    const int slice = tid >> 6;            // 0..7
    const int lanei = part * 8 + slice;    // 0..63
    const int count = NTOK >> g;

    const float* p = out + ((long)b * NTOK + off) * ROWSTRIDE + h * 64 + d;
    float acc = 0.f;
    for (int t = lanei; t < count; t += 64)
        acc += p[(long)t * r * ROWSTRIDE];

    red[tid] = acc;
    __syncthreads();
    if (slice == 0) {
        float sum = red[d];
        #pragma unroll
        for (int k = 1; k < 8; k++) sum += red[k * 64 + d];
        g_partial[(bh * 8 + part) * 64 + d] = sum;
    }
}

// ---------------------------------------------------------------------------
// Kernel 2b: combine partials into g_denom.
// ---------------------------------------------------------------------------
__global__ void __launch_bounds__(64) denom_combine()
{
    const int bh = blockIdx.x;
    const int d  = threadIdx.x;
    float s = 0.f;
    #pragma unroll
    for (int p = 0; p < 8; p++)
        s += g_partial[(bh * 8 + p) * 64 + d];
    g_denom[bh * 64 + d] = s;
}

// ---------------------------------------------------------------------------
// Kernel 3: final normalize + zero uncovered positions (float4).
// ---------------------------------------------------------------------------
__global__ void __launch_bounds__(256) norm_kernel(float4* __restrict__ out4)
{
    const long total4 = (long)2 * NTOK * HEADS * 16;
    long i4 = (long)blockIdx.x * 256 + threadIdx.x;
    if (i4 >= total4) return;

    int  dq = (int)(i4 & 15);
    long t = i4 >> 4;
    int  h = (int)(t % HEADS); t /= HEADS;
    int  n = (int)(t % NTOK);
    int  b = (int)(t / NTOK);

    int g   = h >> 2;
    int r   = 1 << g;
    int off = (g == 2) ? 2 : g;

    float4 v = make_float4(0.f, 0.f, 0.f, 0.f);
    if ((n & (r - 1)) == off) {
        float4 x = out4[i4];
        const float* dn = g_denom + (b * HEADS + h) * 64 + dq * 4;
        v.x = x.x / (dn[0] * 3.0f);
        v.y = x.y / (dn[1] * 3.0f);
        v.z = x.z / (dn[2] * 3.0f);
        v.w = x.w / (dn[3] * 3.0f);
    }
    out4[i4] = v;
}

// ---------------------------------------------------------------------------
extern "C" void kernel_launch(void* const* d_in, const int* in_sizes, int n_in,
                              void* d_out, int out_size)
{
    const float* Q = (const float*)d_in[0];
    const float* K = (const float*)d_in[1];
    const float* V = (const float*)d_in[2];
    float* out = (float*)d_out;

    static int configured = 0;
    if (!configured) {
        cudaFuncSetAttribute(attn_kernel,
                             cudaFuncAttributeMaxDynamicSharedMemorySize, SMEM_BYTES);
        configured = 1;
    }

    attn_kernel<<<dim3(16, 56), 256, SMEM_BYTES>>>(Q, K, V, out);
    denom_partial<<<dim3(2 * HEADS, 8), 512>>>(out);
    denom_combine<<<2 * HEADS, 64>>>();

    const long total4 = (long)2 * NTOK * HEADS * 16;
    int blocks = (int)((total4 + 255) / 256);
    norm_kernel<<<blocks, 256>>>((float4*)out);
}

// round 15
// speedup vs baseline: 3.3629x; 1.0163x over previous
#include <cuda_runtime.h>
#include <cuda_fp16.h>
#include <cstdint>

#define NTOK 8192
#define HEADS 12
#define ROWSTRIDE 768   // HEADS*64 floats between consecutive tokens

__device__ float g_denom[2 * HEADS * 64];
__device__ float g_partial[2 * HEADS * 8 * 64];

// ---------------------------------------------------------------------------
// helpers
// ---------------------------------------------------------------------------
__device__ __forceinline__ float fast_exp2(float x) {
    float y; asm("ex2.approx.ftz.f32 %0, %1;" : "=f"(y) : "f"(x)); return y;
}
__device__ __forceinline__ uint32_t packh2(float lo, float hi) {
    uint32_t r;
    asm("cvt.rn.f16x2.f32 %0, %1, %2;" : "=r"(r) : "f"(hi), "f"(lo));
    return r;
}
__device__ __forceinline__ float2 unpackh2(uint32_t p) {
    __half2 h = *reinterpret_cast<__half2*>(&p);
    return __half22float2(h);
}
__device__ __forceinline__ uint32_t smem_u32(const void* p) {
    uint32_t a;
    asm("{ .reg .u64 t; cvta.to.shared.u64 t, %1; cvt.u32.u64 %0, t; }" : "=r"(a) : "l"(p));
    return a;
}
__device__ __forceinline__ void ldsm4(uint32_t r[4], uint32_t addr) {
    asm volatile("ldmatrix.sync.aligned.m8n8.x4.shared.b16 {%0,%1,%2,%3}, [%4];"
                 : "=r"(r[0]), "=r"(r[1]), "=r"(r[2]), "=r"(r[3]) : "r"(addr));
}
__device__ __forceinline__ void ldsm4t(uint32_t r[4], uint32_t addr) {
    asm volatile("ldmatrix.sync.aligned.m8n8.x4.trans.shared.b16 {%0,%1,%2,%3}, [%4];"
                 : "=r"(r[0]), "=r"(r[1]), "=r"(r[2]), "=r"(r[3]) : "r"(addr));
}
__device__ __forceinline__ void mma16816(float d[4], const uint32_t a[4],
                                         uint32_t b0, uint32_t b1, const float c[4]) {
    asm volatile(
        "mma.sync.aligned.m16n8k16.row.col.f32.f16.f16.f32 "
        "{%0,%1,%2,%3},{%4,%5,%6,%7},{%8,%9},{%10,%11,%12,%13};"
        : "=f"(d[0]), "=f"(d[1]), "=f"(d[2]), "=f"(d[3])
        : "r"(a[0]), "r"(a[1]), "r"(a[2]), "r"(a[3]), "r"(b0), "r"(b1),
          "f"(c[0]), "f"(c[1]), "f"(c[2]), "f"(c[3]));
}
__device__ __forceinline__ void cp_async16(uint32_t dst, const void* src) {
    asm volatile("cp.async.cg.shared.global [%0], [%1], 16;" :: "r"(dst), "l"(src));
}
#define CP_COMMIT() asm volatile("cp.async.commit_group;" ::: "memory")
#define CP_WAIT(n)  asm volatile("cp.async.wait_group %0;" :: "n"(n) : "memory")

__device__ __forceinline__ float4 lds128f(uint32_t addr) {
    float4 v;
    asm volatile("ld.shared.v4.f32 {%0,%1,%2,%3}, [%4];"
                 : "=f"(v.x), "=f"(v.y), "=f"(v.z), "=f"(v.w) : "r"(addr));
    return v;
}

// swizzled byte offset of (row, 16B-chunk) in a [rows][64 half] tile (128B/row)
#define SWB(row, c8) (((uint32_t)(row) << 7) + ((((uint32_t)(c8)) ^ ((uint32_t)(row) & 7u)) << 4))

// smem layout
#define O_RAWK 0            // 32 KB raw fp32 K tile
#define O_RAWV 32768        // 32 KB raw fp32 V tile
#define O_BUF  65536        // 2 x 64 KB fp16 buffer sets
#define B_KH 0
#define B_KL 16384
#define B_VH 32768
#define B_VL 49152
#define SMEM_BYTES (65536 + 2 * 65536)   // 192 KB

#define C11 (1.0f / 2048.0f)
#define C22 (C11 * C11)

// convert raw chunk c (K and V) into fp16 buffer set dst
__device__ __forceinline__ void convert_chunk(uint32_t sb, uint32_t dst, int c) {
    const int row = c >> 4, f4 = c & 15;
    const uint32_t o8 = SWB(row, f4 >> 1) + ((uint32_t)(f4 & 1) << 3);
    {
        float4 v = lds128f(sb + O_RAWK + (uint32_t)c * 16);
        uint32_t h0 = packh2(v.x, v.y), h1 = packh2(v.z, v.w);
        float2 f0 = unpackh2(h0), f1 = unpackh2(h1);
        uint32_t l0_ = packh2((v.x - f0.x) * 2048.f, (v.y - f0.y) * 2048.f);
        uint32_t l1_ = packh2((v.z - f1.x) * 2048.f, (v.w - f1.y) * 2048.f);
        asm volatile("st.shared.v2.b32 [%0], {%1,%2};" :: "r"(dst + B_KH + o8), "r"(h0), "r"(h1));
        asm volatile("st.shared.v2.b32 [%0], {%1,%2};" :: "r"(dst + B_KL + o8), "r"(l0_), "r"(l1_));
    }
    {
        float4 v = lds128f(sb + O_RAWV + (uint32_t)c * 16);
        uint32_t h0 = packh2(v.x, v.y), h1 = packh2(v.z, v.w);
        float2 f0 = unpackh2(h0), f1 = unpackh2(h1);
        uint32_t l0_ = packh2((v.x - f0.x) * 2048.f, (v.y - f0.y) * 2048.f);
        uint32_t l1_ = packh2((v.z - f1.x) * 2048.f, (v.w - f1.y) * 2048.f);
        asm volatile("st.shared.v2.b32 [%0], {%1,%2};" :: "r"(dst + B_VH + o8), "r"(h0), "r"(h1));
        asm volatile("st.shared.v2.b32 [%0], {%1,%2};" :: "r"(dst + B_VL + o8), "r"(l0_), "r"(l1_));
    }
}

// issue cp.async for chunk c of (K,V) tile at kb/vb; one commit group
__device__ __forceinline__ void issue_chunk(uint32_t sb, int c,
                                            const float* kb, const float* vb,
                                            long rstride) {
    const int row = c >> 4, f4 = c & 15;
    cp_async16(sb + O_RAWK + (uint32_t)c * 16, kb + (long)row * rstride + (f4 << 2));
    cp_async16(sb + O_RAWV + (uint32_t)c * 16, vb + (long)row * rstride + (f4 << 2));
    CP_COMMIT();
}

// ---------------------------------------------------------------------------
// Kernel 1: software-pipelined scaled-split-fp16 mma.sync flash attention.
// CTA = (q-tile of 128 rows, job). 8 warps x 16 rows. BLOCK_N = 128.
// GEMM1(j+1) is interleaved with softmax(j)+GEMM2(j) via a ping-pong
// accumulator block, keeping the tensor pipe fed through the softmax
// dependency bubble. Convert/refill interleaved per j as in R14.
// ---------------------------------------------------------------------------
__global__ void __launch_bounds__(256) attn_kernel(
    const float* __restrict__ Q,
    const float* __restrict__ K,
    const float* __restrict__ V,
    float* __restrict__ out)
{
    extern __shared__ __align__(16) char smem_raw[];
    const uint32_t sb = smem_u32(smem_raw);
    const uint32_t buf0 = sb + O_BUF;
    const uint32_t buf1 = sb + O_BUF + 65536u;

    const int tid  = threadIdx.x;
    const int wid  = tid >> 5;
    const int lane = tid & 31;

    // ---- decode job ----
    const int job = blockIdx.y;
    int g, b, seg, hl;
    if (job < 32)      { g = 0; hl = job & 3;  seg = (job >> 2) & 3; b = job >> 4; }
    else if (job < 48) { int l = job - 32; g = 1; hl = l & 3; seg = (l >> 2) & 1; b = l >> 3; }
    else               { int l = job - 48; g = 2; hl = l & 3; seg = 0;            b = l >> 2; }
    const int r   = 1 << g;
    const int s   = 2048 << g;
    const int off = (g == 2) ? 2 : g;
    const int h   = g * 4 + hl;
    const long rstride = (long)r * ROWSTRIDE;
    const long segbase = ((long)b * NTOK + (long)seg * s + off) * ROWSTRIDE + h * 64;
    const long qbase   = segbase + (long)blockIdx.x * 128 * rstride;

    // ---- prologue: cp.async raw tile 0 (single group) ----
    {
        const float* kb = K + segbase;
        const float* vb = V + segbase;
        #pragma unroll
        for (int i = 0; i < 8; i++) {
            int c = tid + (i << 8);
            int row = c >> 4, f4 = c & 15;
            cp_async16(sb + O_RAWK + (uint32_t)c * 16, kb + (long)row * rstride + (f4 << 2));
            cp_async16(sb + O_RAWV + (uint32_t)c * 16, vb + (long)row * rstride + (f4 << 2));
        }
        CP_COMMIT();
    }

    // ---- stage Q (pre-scaled) into buf0.KH/KL, extract fragments ----
    const float qs = 0.125f * 1.4426950408889634f;
    #pragma unroll
    for (int i = 0; i < 8; i++) {
        int linear = tid + (i << 8);
        int row = linear >> 4, f4 = linear & 15;
        float4 v = *(const float4*)(Q + qbase + (long)row * rstride + (f4 << 2));
        v.x *= qs; v.y *= qs; v.z *= qs; v.w *= qs;
        uint32_t h0 = packh2(v.x, v.y), h1 = packh2(v.z, v.w);
        float2 f0 = unpackh2(h0), f1 = unpackh2(h1);
        uint32_t l0_ = packh2((v.x - f0.x) * 2048.f, (v.y - f0.y) * 2048.f);
        uint32_t l1_ = packh2((v.z - f1.x) * 2048.f, (v.w - f1.y) * 2048.f);
        uint32_t o8 = SWB(row, f4 >> 1) + ((uint32_t)(f4 & 1) << 3);
        asm volatile("st.shared.v2.b32 [%0], {%1,%2};" :: "r"(buf0 + B_KH + o8), "r"(h0), "r"(h1));
        asm volatile("st.shared.v2.b32 [%0], {%1,%2};" :: "r"(buf0 + B_KL + o8), "r"(l0_), "r"(l1_));
    }
    __syncthreads();

    uint32_t qfh[4][4], qfl[4][4];
    {
        uint32_t row = (uint32_t)(wid * 16 + (lane & 15));
        #pragma unroll
        for (int ks = 0; ks < 4; ks++) {
            uint32_t chunk = (uint32_t)(lane >> 4) + ((uint32_t)ks << 1);
            ldsm4(qfh[ks], buf0 + B_KH + SWB(row, chunk));
            ldsm4(qfl[ks], buf0 + B_KL + SWB(row, chunk));
        }
    }
    __syncthreads();   // all warps read Q before convert overwrites buf0

    // ---- wait raw tile0, convert to buf0, issue tile1 (per-chunk groups) ----
    CP_WAIT(0);
    {
        const float* kb = K + segbase + (long)128 * rstride;
        const float* vb = V + segbase + (long)128 * rstride;
        #pragma unroll
        for (int j = 0; j < 8; j++) {
            int c = tid + (j << 8);
            convert_chunk(sb, buf0, c);
            issue_chunk(sb, c, kb, vb, rstride);
        }
    }
    __syncthreads();   // buf0 ready

    float oacc[8][4];
    #pragma unroll
    for (int i = 0; i < 8; i++)
        #pragma unroll
        for (int e = 0; e < 4; e++) oacc[i][e] = 0.f;
    float lr0 = 0.f, lr1 = 0.f;

    for (int kt = 0; kt < 16; kt++) {
        const uint32_t cur = (kt & 1) ? buf1 : buf0;
        const uint32_t nxt = (kt & 1) ? buf0 : buf1;
        int nt = (kt + 2 < 16) ? (kt + 2) : 15;
        const float* kb2 = K + segbase + (long)(nt * 128) * rstride;
        const float* vb2 = V + segbase + (long)(nt * 128) * rstride;
        const bool doconv = (kt < 15);

        float ocor[8][4];
        #pragma unroll
        for (int i = 0; i < 8; i++)
            #pragma unroll
            for (int e = 0; e < 4; e++) ocor[i][e] = 0.f;

        // ping-pong GEMM1 accumulator block: [parity][acc 0..5][4]
        // acc 0,1 = hh(n-lo,n-hi); 2,3 = mid; 4,5 = ll
        float ablk[2][6][4];

        // ---- GEMM1 block j=0 into ablk[0] ----
        #pragma unroll
        for (int a = 0; a < 6; a++)
            #pragma unroll
            for (int e = 0; e < 4; e++) ablk[0][a][e] = 0.f;
        {
            uint32_t row = (uint32_t)(lane & 15);
            #pragma unroll
            for (int ks = 0; ks < 4; ks++) {
                uint32_t chunk = (uint32_t)(lane >> 4) + ((uint32_t)ks << 1);
                uint32_t kh[4], kl[4];
                ldsm4(kh, cur + B_KH + SWB(row, chunk));
                ldsm4(kl, cur + B_KL + SWB(row, chunk));
                mma16816(ablk[0][0], qfh[ks], kh[0], kh[2], ablk[0][0]);
                mma16816(ablk[0][1], qfh[ks], kh[1], kh[3], ablk[0][1]);
                mma16816(ablk[0][2], qfh[ks], kl[0], kl[2], ablk[0][2]);
                mma16816(ablk[0][3], qfh[ks], kl[1], kl[3], ablk[0][3]);
                mma16816(ablk[0][2], qfl[ks], kh[0], kh[2], ablk[0][2]);
                mma16816(ablk[0][3], qfl[ks], kh[1], kh[3], ablk[0][3]);
                mma16816(ablk[0][4], qfl[ks], kl[0], kl[2], ablk[0][4]);
                mma16816(ablk[0][5], qfl[ks], kl[1], kl[3], ablk[0][5]);
            }
        }

        #pragma unroll
        for (int j = 0; j < 8; j++) {
            const int pj = j & 1, nj = pj ^ 1;

            // ---- softmax(j) from ablk[pj] ----
            uint32_t pfh[4], pfl[4], pfu[4];
            {
                float s0 = ablk[pj][0][0] + ablk[pj][2][0] * C11 + ablk[pj][4][0] * C22;
                float s1 = ablk[pj][0][1] + ablk[pj][2][1] * C11 + ablk[pj][4][1] * C22;
                float s2 = ablk[pj][0][2] + ablk[pj][2][2] * C11 + ablk[pj][4][2] * C22;
                float s3 = ablk[pj][0][3] + ablk[pj][2][3] * C11 + ablk[pj][4][3] * C22;
                float s4 = ablk[pj][1][0] + ablk[pj][3][0] * C11 + ablk[pj][5][0] * C22;
                float s5 = ablk[pj][1][1] + ablk[pj][3][1] * C11 + ablk[pj][5][1] * C22;
                float s6 = ablk[pj][1][2] + ablk[pj][3][2] * C11 + ablk[pj][5][2] * C22;
                float s7 = ablk[pj][1][3] + ablk[pj][3][3] * C11 + ablk[pj][5][3] * C22;
                float p0 = fast_exp2(s0), p1 = fast_exp2(s1);
                float p2 = fast_exp2(s2), p3 = fast_exp2(s3);
                float p4 = fast_exp2(s4), p5 = fast_exp2(s5);
                float p6 = fast_exp2(s6), p7 = fast_exp2(s7);
                lr0 += (p0 + p1) + (p4 + p5);
                lr1 += (p2 + p3) + (p6 + p7);
                pfh[0] = packh2(p0, p1);
                pfh[1] = packh2(p2, p3);
                pfh[2] = packh2(p4, p5);
                pfh[3] = packh2(p6, p7);
                float2 f;
                float d0, d1;
                f = unpackh2(pfh[0]); d0 = p0 - f.x; d1 = p1 - f.y;
                pfl[0] = packh2(d0 * 2048.f, d1 * 2048.f); pfu[0] = packh2(d0, d1);
                f = unpackh2(pfh[1]); d0 = p2 - f.x; d1 = p3 - f.y;
                pfl[1] = packh2(d0 * 2048.f, d1 * 2048.f); pfu[1] = packh2(d0, d1);
                f = unpackh2(pfh[2]); d0 = p4 - f.x; d1 = p5 - f.y;
                pfl[2] = packh2(d0 * 2048.f, d1 * 2048.f); pfu[2] = packh2(d0, d1);
                f = unpackh2(pfh[3]); d0 = p6 - f.x; d1 = p7 - f.y;
                pfl[3] = packh2(d0 * 2048.f, d1 * 2048.f); pfu[3] = packh2(d0, d1);
            }

            // ---- zero ablk[nj] for GEMM1(j+1) ----
            if (j < 7) {
                #pragma unroll
                for (int a = 0; a < 6; a++)
                    #pragma unroll
                    for (int e = 0; e < 4; e++) ablk[nj][a][e] = 0.f;
            }

            // ---- fused: GEMM1(j+1) ks=i interleaved with GEMM2(j) dp=i ----
            uint32_t nrow = ((uint32_t)(j + 1) << 4) + (uint32_t)(lane & 15);
            uint32_t jr = ((uint32_t)j << 4) + (uint32_t)(lane & 7) + ((((uint32_t)lane >> 3) & 1u) << 3);
            #pragma unroll
            for (int i = 0; i < 4; i++) {
                uint32_t chunk = (uint32_t)(lane >> 4) + ((uint32_t)i << 1);
                if (j < 7) {
                    uint32_t kh[4], kl[4];
                    ldsm4(kh, cur + B_KH + SWB(nrow, chunk));
                    ldsm4(kl, cur + B_KL + SWB(nrow, chunk));
                    mma16816(ablk[nj][0], qfh[i], kh[0], kh[2], ablk[nj][0]);
                    mma16816(ablk[nj][1], qfh[i], kh[1], kh[3], ablk[nj][1]);
                    mma16816(ablk[nj][2], qfh[i], kl[0], kl[2], ablk[nj][2]);
                    mma16816(ablk[nj][3], qfh[i], kl[1], kl[3], ablk[nj][3]);
                    mma16816(ablk[nj][2], qfl[i], kh[0], kh[2], ablk[nj][2]);
                    mma16816(ablk[nj][3], qfl[i], kh[1], kh[3], ablk[nj][3]);
                    mma16816(ablk[nj][4], qfl[i], kl[0], kl[2], ablk[nj][4]);
                    mma16816(ablk[nj][5], qfl[i], kl[1], kl[3], ablk[nj][5]);
                }
                {
                    uint32_t vh[4], vl[4];
                    ldsm4t(vh, cur + B_VH + SWB(jr, chunk));
                    ldsm4t(vl, cur + B_VL + SWB(jr, chunk));
                    mma16816(oacc[2*i],   pfh, vh[0], vh[1], oacc[2*i]);
                    mma16816(oacc[2*i+1], pfh, vh[2], vh[3], oacc[2*i+1]);
                    mma16816(ocor[2*i],   pfh, vl[0], vl[1], ocor[2*i]);
                    mma16816(ocor[2*i+1], pfh, vl[2], vl[3], ocor[2*i+1]);
                    mma16816(ocor[2*i],   pfl, vh[0], vh[1], ocor[2*i]);
                    mma16816(ocor[2*i+1], pfl, vh[2], vh[3], ocor[2*i+1]);
                    mma16816(ocor[2*i],   pfu, vl[0], vl[1], ocor[2*i]);   // == pfl*vu
                    mma16816(ocor[2*i+1], pfu, vl[2], vl[3], ocor[2*i+1]);
                }
            }

            // ---- interleaved: convert chunk j of tile kt+1, refill tile kt+2 ----
            if (doconv) {
                CP_WAIT(7);                       // oldest group = chunk j of tile kt+1
                int c = tid + (j << 8);
                convert_chunk(sb, nxt, c);
                issue_chunk(sb, c, kb2, vb2, rstride);
            }
        }

        // fold correction into main accumulator (per tile; same as R13/R14)
        #pragma unroll
        for (int i = 0; i < 8; i++)
            #pragma unroll
            for (int e = 0; e < 4; e++)
                oacc[i][e] = fmaf(ocor[i][e], C11, oacc[i][e]);

        __syncthreads();   // all warps done with cur before next iter overwrites it
    }
    CP_WAIT(0);            // retire trailing dummy groups before exit

    // ---- epilogue: reduce l across quad, normalize, write ----
    lr0 += __shfl_xor_sync(0xffffffffu, lr0, 1);
    lr0 += __shfl_xor_sync(0xffffffffu, lr0, 2);
    lr1 += __shfl_xor_sync(0xffffffffu, lr1, 1);
    lr1 += __shfl_xor_sync(0xffffffffu, lr1, 2);
    const float inv0 = 1.f / lr0;
    const float inv1 = 1.f / lr1;

    const int gq = lane >> 2, t4 = lane & 3;
    float* r0p = out + qbase + (long)(wid * 16 + gq) * rstride;
    float* r1p = out + qbase + (long)(wid * 16 + gq + 8) * rstride;
    #pragma unroll
    for (int dt = 0; dt < 8; dt++) {
        float2 w0 = make_float2(oacc[dt][0] * inv0, oacc[dt][1] * inv0);
        float2 w1 = make_float2(oacc[dt][2] * inv1, oacc[dt][3] * inv1);
        *(float2*)(r0p + dt * 8 + 2 * t4) = w0;
        *(float2*)(r1p + dt * 8 + 2 * t4) = w1;
    }
}

// ---------------------------------------------------------------------------
// Kernel 2a: per-(b,h) partial sums over covered positions (8 parts).
// ---------------------------------------------------------------------------
__global__ void __launch_bounds__(512) denom_partial(const float* __restrict__ out)
{
    __shared__ float red[512];
    const int bh   = blockIdx.x;      // 0..23
    const int part = blockIdx.y;      // 0..7
    const int b  = bh / HEADS;
    const int h  = bh % HEADS;
    const int g  = h >> 2;
    const int r  = 1 << g;
    const int off = (g == 2) ? 2 : g;

    const int tid   = threadIdx.x;
    const int d     = tid & 63;
    const int slice = tid >> 6;            // 0..7
    const int lanei = part * 8 + slice;    // 0..63
    const int count = NTOK >> g;

    const float* p = out + ((long)b * NTOK + off) * ROWSTRIDE + h * 64 + d;
    float acc = 0.f;
    for (int t = lanei; t < count; t += 64)
        acc += p[(long)t * r * ROWSTRIDE];

    red[tid] = acc;
    __syncthreads();
    if (slice == 0) {
        float sum = red[d];
        #pragma unroll
        for (int k = 1; k < 8; k++) sum += red[k * 64 + d];
        g_partial[(bh * 8 + part) * 64 + d] = sum;
    }
}

// ---------------------------------------------------------------------------
// Kernel 2b: combine partials into g_denom.
// ---------------------------------------------------------------------------
__global__ void __launch_bounds__(64) denom_combine()
{
    const int bh = blockIdx.x;
    const int d  = threadIdx.x;
    float s = 0.f;
    #pragma unroll
    for (int p = 0; p < 8; p++)
        s += g_partial[(bh * 8 + p) * 64 + d];
    g_denom[bh * 64 + d] = s;
}

// ---------------------------------------------------------------------------
// Kernel 3: final normalize + zero uncovered positions (float4).
// ---------------------------------------------------------------------------
__global__ void __launch_bounds__(256) norm_kernel(float4* __restrict__ out4)
{
    const long total4 = (long)2 * NTOK * HEADS * 16;
    long i4 = (long)blockIdx.x * 256 + threadIdx.x;
    if (i4 >= total4) return;

    int  dq = (int)(i4 & 15);
    long t = i4 >> 4;
    int  h = (int)(t % HEADS); t /= HEADS;
    int  n = (int)(t % NTOK);
    int  b = (int)(t / NTOK);

    int g   = h >> 2;
    int r   = 1 << g;
    int off = (g == 2) ? 2 : g;

    float4 v = make_float4(0.f, 0.f, 0.f, 0.f);
    if ((n & (r - 1)) == off) {
        float4 x = out4[i4];
        const float* dn = g_denom + (b * HEADS + h) * 64 + dq * 4;
        v.x = x.x / (dn[0] * 3.0f);
        v.y = x.y / (dn[1] * 3.0f);
        v.z = x.z / (dn[2] * 3.0f);
        v.w = x.w / (dn[3] * 3.0f);
    }
    out4[i4] = v;
}

// ---------------------------------------------------------------------------
extern "C" void kernel_launch(void* const* d_in, const int* in_sizes, int n_in,
                              void* d_out, int out_size)
{
    const float* Q = (const float*)d_in[0];
    const float* K = (const float*)d_in[1];
    const float* V = (const float*)d_in[2];
    float* out = (float*)d_out;

    static int configured = 0;
    if (!configured) {
        cudaFuncSetAttribute(attn_kernel,
                             cudaFuncAttributeMaxDynamicSharedMemorySize, SMEM_BYTES);
        configured = 1;
    }

    attn_kernel<<<dim3(16, 56), 256, SMEM_BYTES>>>(Q, K, V, out);
    denom_partial<<<dim3(2 * HEADS, 8), 512>>>(out);
    denom_combine<<<2 * HEADS, 64>>>();

    const long total4 = (long)2 * NTOK * HEADS * 16;
    int blocks = (int)((total4 + 255) / 256);
    norm_kernel<<<blocks, 256>>>((float4*)out);
}